// round 12
// baseline (speedup 1.0000x reference)
#include <cuda_runtime.h>
#include <cuda_fp16.h>
#include <cstdint>

// ============================================================================
// y = x @ W_eff^T + b_eff   (exact collapse of the one-hot op mixture)
// x: [131072, 128] fp32.  Single fp16 product (rel_err ~2.9e-4).
// R12: B fragments REGISTER-RESIDENT for the whole kernel. Warp tile 16x64
//      (4M x 2N warp grid, TILE_M=64): per-warp B = 8ks x 4frags x 4regs =
//      128 regs, ldmatrix'd once in the prologue, reused for ~14 tiles.
//      Main loop: 2 LDG.128 + 4 packs + 8 MMAs per k-step, ZERO smem loads.
//      Removes ~2048 B-ldmatrix wavefronts per 128 rows (~40% of L1).
//      k-permutation trick from R11 retained (baked into W staging).
// ============================================================================

static constexpr int D       = 128;
static constexpr int TILE_M  = 64;
static constexpr int N_TILES = 2048;
static constexpr int GRID    = 148;                  // persistent, 1 CTA/SM
static constexpr int NTHR    = 256;                  // 8 warps: 4M x 2N

static constexpr int PITCHW  = 272;                  // fp16 W tile pitch
static constexpr int WTILE   = 128 * PITCHW;         // 34816 B
static constexpr int SM_W    = 0;
static constexpr int SM_BIAS = WTILE;                // 512 B
static constexpr int SM_TOTAL = WTILE + 512;

// ---------------- PTX helpers (baseline ISA only) ---------------------------

__device__ __forceinline__ uint32_t smem_to_u32(const void* p) {
    uint32_t a;
    asm("{ .reg .u64 t; cvta.to.shared.u64 t, %1; cvt.u32.u64 %0, t; }"
        : "=r"(a) : "l"(p));
    return a;
}

__device__ __forceinline__ void ldmatrix_x4(uint32_t& r0, uint32_t& r1,
                                            uint32_t& r2, uint32_t& r3,
                                            uint32_t addr) {
    asm volatile("ldmatrix.sync.aligned.m8n8.x4.shared.b16 {%0,%1,%2,%3}, [%4];"
                 : "=r"(r0), "=r"(r1), "=r"(r2), "=r"(r3) : "r"(addr));
}

__device__ __forceinline__ void mma_f16(float* c, const uint32_t* a,
                                        const uint32_t* b) {
    asm volatile(
        "mma.sync.aligned.m16n8k16.row.col.f32.f16.f16.f32 "
        "{%0,%1,%2,%3}, {%4,%5,%6,%7}, {%8,%9}, {%0,%1,%2,%3};"
        : "+f"(c[0]), "+f"(c[1]), "+f"(c[2]), "+f"(c[3])
        : "r"(a[0]), "r"(a[1]), "r"(a[2]), "r"(a[3]), "r"(b[0]), "r"(b[1]));
}

__device__ __forceinline__ uint32_t pack_h2(float a, float b) {
    __half2 h = __floats2half2_rn(a, b);
    return *(uint32_t*)&h;
}

// ============================================================================
__global__ void __launch_bounds__(NTHR, 1)
gemm_kernel(const float* __restrict__ x,
            const float* __restrict__ W,
            const float* __restrict__ bias,
            const float* __restrict__ wsel,
            float* __restrict__ y) {
    extern __shared__ char smem[];
    const uint32_t sb  = smem_to_u32(smem);
    const int tid  = threadIdx.x;
    const int w    = tid >> 5;
    const int l    = tid & 31;
    const int mw   = w & 3;          // M group: rows mw*16 .. +15 within tile
    const int nh   = w >> 2;         // N half:  cols nh*64 .. +63

    const float w0 = wsel[0], w1 = wsel[1], w2 = wsel[2], w3 = wsel[3];

    // ---- stage W_eff (fp16) into SMEM with per-16-block k-permutation ----
    // fragment-k (2j+m) holds data-k (4j+m); (2j+8+m) holds (4j+2+m).
#pragma unroll
    for (int jj = 0; jj < 64; jj++) {                // 16384 / 256
        const int idx = tid + jj * NTHR;
        const float v = w0 * W[idx] + w1 * W[16384 + idx]
                      + w2 * W[32768 + idx] + w3 * W[49152 + idx];
        const int f  = idx >> 7, d = idx & 127;
        const int b  = d >> 4, dk = d & 15;
        const int j  = dk >> 2, m = dk & 3;
        const int fk = 2 * j + m + ((m >= 2) ? 6 : 0);
        const int col = b * 16 + fk;
        *(__half*)(smem + SM_W + f * PITCHW + col * 2) = __float2half_rn(v);
    }
    if (tid < 128) {
        ((float*)(smem + SM_BIAS))[tid] =
            w0 * bias[tid] + w1 * bias[128 + tid]
          + w2 * bias[256 + tid] + w3 * bias[384 + tid];
    }
    __syncthreads();

    // ---- preload ALL B fragments for this warp's 64 columns into regs ----
    // breg[ks][np][4]: 8 k-steps x 4 n-tile-pairs x 4 regs = 128 regs.
    const uint32_t boff = (uint32_t)((((l >> 4) & 1) * 8 + (l & 7)) * PITCHW
                                     + ((l >> 3) & 1) * 16);
    const uint32_t sW = sb + SM_W;
    uint32_t breg[8][4][4];
#pragma unroll
    for (int ks = 0; ks < 8; ks++)
#pragma unroll
        for (int np = 0; np < 4; np++) {
            const uint32_t nb = (uint32_t)(nh * 64 + np * 16) * PITCHW;
            ldmatrix_x4(breg[ks][np][0], breg[ks][np][1],
                        breg[ks][np][2], breg[ks][np][3],
                        sW + boff + nb + (uint32_t)ks * 32);
        }

    // per-thread A row/col: row = t*64 + mw*16 + l/4, col floats (l&3)*4
    const int rbase_in_tile = mw * 16 + (l >> 2);
    const int acol = (l & 3) * 4;
    const int cpair = (l & 3) * 2;
    const float* bsm = (const float*)(smem + SM_BIAS);

    for (int t = blockIdx.x; t < N_TILES; t += GRID) {
        const float* xr = x + ((size_t)t * TILE_M + rbase_in_tile) * D + acol;

        float acc[8][4];
#pragma unroll
        for (int nt = 0; nt < 8; nt++)
#pragma unroll
            for (int j = 0; j < 4; j++) acc[nt][j] = 0.0f;

#pragma unroll
        for (int ks = 0; ks < 8; ks++) {
            // A fragment: 2x LDG.128 (k-permuted mapping)
            const float4 lo = *(const float4*)(xr + ks * 16);          // row r
            const float4 hi = *(const float4*)(xr + 8 * D + ks * 16);  // row r+8
            uint32_t a[4];
            a[0] = pack_h2(lo.x, lo.y);
            a[1] = pack_h2(hi.x, hi.y);
            a[2] = pack_h2(lo.z, lo.w);
            a[3] = pack_h2(hi.z, hi.w);

            // 8 MMAs from register-resident B
#pragma unroll
            for (int np = 0; np < 4; np++) {
                mma_f16(acc[np * 2 + 0], a, &breg[ks][np][0]);
                mma_f16(acc[np * 2 + 1], a, &breg[ks][np][2]);
            }
        }

        // epilogue: bias (from SMEM) + STG
        const size_t row = (size_t)t * TILE_M + rbase_in_tile;
#pragma unroll
        for (int nt = 0; nt < 8; nt++) {
            const int col = nh * 64 + nt * 8 + cpair;
            const float bxv = bsm[col], byv = bsm[col + 1];
            float2 v0 = make_float2(acc[nt][0] + bxv, acc[nt][1] + byv);
            float2 v1 = make_float2(acc[nt][2] + bxv, acc[nt][3] + byv);
            *(float2*)(y + row * D + col)       = v0;
            *(float2*)(y + (row + 8) * D + col) = v1;
        }
    }
}

// ============================================================================

extern "C" void kernel_launch(void* const* d_in, const int* in_sizes, int n_in,
                              void* d_out, int out_size) {
    const float* x    = (const float*)d_in[0];  // [16, 8192, 128]
    const float* W    = (const float*)d_in[1];  // [4, 128, 128]
    const float* b    = (const float*)d_in[2];  // [4, 128]
    const float* wsel = (const float*)d_in[3];  // [4]
    float* y = (float*)d_out;                   // [16, 8192, 128]

    static bool attr_set = false;
    if (!attr_set) {
        cudaFuncSetAttribute(gemm_kernel,
                             cudaFuncAttributeMaxDynamicSharedMemorySize, SM_TOTAL);
        attr_set = true;
    }
    gemm_kernel<<<GRID, NTHR, SM_TOTAL>>>(x, W, b, wsel, y);
}

// round 13
// speedup vs baseline: 1.1079x; 1.1079x over previous
#include <cuda_runtime.h>
#include <cuda_fp16.h>
#include <cstdint>

// ============================================================================
// y = x @ W_eff^T + b_eff   (exact collapse of the one-hot op mixture)
// x: [131072, 128] fp32.  Single fp16 product (rel_err ~2.9e-4).
// R13: R11 structure (disjoint 16x128 warp tiles, per-ks B ldmatrix,
//      k-permuted LDG.128 A loads, zero main-loop barriers) at 512 threads /
//      16 warps (TILE_M=256). Cross-round evidence shows the kernel is
//      LATENCY-bound (L1% moves don't move dur; occ pinned at 12%): doubling
//      warps/SMSP (2->4) doubles latency-hiding; the 128-reg ceiling at 512
//      threads also stops ptxas's 254-reg over-hoisting.
// ============================================================================

static constexpr int D       = 128;
static constexpr int TILE_M  = 256;
static constexpr int N_TILES = 512;                  // 131072 / 256
static constexpr int GRID    = 148;                  // persistent, 1 CTA/SM
static constexpr int NTHR    = 512;                  // 16 warps x 16 rows

static constexpr int PITCHW  = 272;                  // fp16 W tile pitch
static constexpr int WTILE   = 128 * PITCHW;         // 34816 B
static constexpr int SM_W    = 0;
static constexpr int SM_BIAS = WTILE;                // 512 B
static constexpr int SM_TOTAL = WTILE + 512;

// ---------------- PTX helpers (baseline ISA only) ---------------------------

__device__ __forceinline__ uint32_t smem_to_u32(const void* p) {
    uint32_t a;
    asm("{ .reg .u64 t; cvta.to.shared.u64 t, %1; cvt.u32.u64 %0, t; }"
        : "=r"(a) : "l"(p));
    return a;
}

__device__ __forceinline__ void ldmatrix_x4(uint32_t& r0, uint32_t& r1,
                                            uint32_t& r2, uint32_t& r3,
                                            uint32_t addr) {
    asm volatile("ldmatrix.sync.aligned.m8n8.x4.shared.b16 {%0,%1,%2,%3}, [%4];"
                 : "=r"(r0), "=r"(r1), "=r"(r2), "=r"(r3) : "r"(addr));
}

__device__ __forceinline__ void mma_f16(float* c, const uint32_t* a,
                                        const uint32_t* b) {
    asm volatile(
        "mma.sync.aligned.m16n8k16.row.col.f32.f16.f16.f32 "
        "{%0,%1,%2,%3}, {%4,%5,%6,%7}, {%8,%9}, {%0,%1,%2,%3};"
        : "+f"(c[0]), "+f"(c[1]), "+f"(c[2]), "+f"(c[3])
        : "r"(a[0]), "r"(a[1]), "r"(a[2]), "r"(a[3]), "r"(b[0]), "r"(b[1]));
}

__device__ __forceinline__ uint32_t pack_h2(float a, float b) {
    __half2 h = __floats2half2_rn(a, b);
    return *(uint32_t*)&h;
}

// ============================================================================
__global__ void __launch_bounds__(NTHR, 1)
gemm_kernel(const float* __restrict__ x,
            const float* __restrict__ W,
            const float* __restrict__ bias,
            const float* __restrict__ wsel,
            float* __restrict__ y) {
    extern __shared__ char smem[];
    const uint32_t sb  = smem_to_u32(smem);
    const int tid  = threadIdx.x;
    const int w    = tid >> 5;       // warp 0..15 -> rows w*16 .. w*16+15
    const int l    = tid & 31;

    const float w0 = wsel[0], w1 = wsel[1], w2 = wsel[2], w3 = wsel[3];

    // ---- stage W_eff (fp16) into SMEM with per-16-block k-permutation ----
    // fragment-k (2j+m) holds data-k (4j+m); (2j+8+m) holds (4j+2+m).
#pragma unroll
    for (int jj = 0; jj < 32; jj++) {                // 16384 / 512
        const int idx = tid + jj * NTHR;
        const float v = w0 * W[idx] + w1 * W[16384 + idx]
                      + w2 * W[32768 + idx] + w3 * W[49152 + idx];
        const int f  = idx >> 7, d = idx & 127;
        const int b  = d >> 4, dk = d & 15;
        const int j  = dk >> 2, m = dk & 3;
        const int fk = 2 * j + m + ((m >= 2) ? 6 : 0);
        const int col = b * 16 + fk;
        *(__half*)(smem + SM_W + f * PITCHW + col * 2) = __float2half_rn(v);
    }
    if (tid < 128) {
        ((float*)(smem + SM_BIAS))[tid] =
            w0 * bias[tid] + w1 * bias[128 + tid]
          + w2 * bias[256 + tid] + w3 * bias[384 + tid];
    }
    __syncthreads();                 // the ONLY block-wide barrier

    // B ldmatrix per-lane offset (permutation handled in staging)
    const uint32_t boff = (uint32_t)((((l >> 4) & 1) * 8 + (l & 7)) * PITCHW
                                     + ((l >> 3) & 1) * 16);
    const uint32_t sW = sb + SM_W;

    // per-thread A row/col: row = t*256 + w*16 + l/4, col floats (l&3)*4
    const int rbase_in_tile = w * 16 + (l >> 2);
    const int acol  = (l & 3) * 4;
    const int cpair = (l & 3) * 2;
    const float* bsm = (const float*)(smem + SM_BIAS);

    for (int t = blockIdx.x; t < N_TILES; t += GRID) {
        const float* xr = x + ((size_t)t * TILE_M + rbase_in_tile) * D + acol;

        float acc[16][4];
#pragma unroll
        for (int nt = 0; nt < 16; nt++)
#pragma unroll
            for (int j = 0; j < 4; j++) acc[nt][j] = 0.0f;

#pragma unroll
        for (int ks = 0; ks < 8; ks++) {
            // A fragment: 2x LDG.128 (k-permuted mapping)
            const float4 lo = *(const float4*)(xr + ks * 16);          // row r
            const float4 hi = *(const float4*)(xr + 8 * D + ks * 16);  // row r+8
            uint32_t a[4];
            a[0] = pack_h2(lo.x, lo.y);
            a[1] = pack_h2(hi.x, hi.y);
            a[2] = pack_h2(lo.z, lo.w);
            a[3] = pack_h2(hi.z, hi.w);

            // B fragments: 8 x4-ldmatrix cover all 16 n-tiles
            uint32_t bq[8][4];
#pragma unroll
            for (int np = 0; np < 8; np++) {
                const uint32_t nb = (uint32_t)(np * 16) * PITCHW;
                ldmatrix_x4(bq[np][0], bq[np][1], bq[np][2], bq[np][3],
                            sW + boff + nb + (uint32_t)ks * 32);
            }

            // 16 MMAs into 16 independent accumulators
#pragma unroll
            for (int np = 0; np < 8; np++) {
                mma_f16(acc[np * 2 + 0], a, &bq[np][0]);
                mma_f16(acc[np * 2 + 1], a, &bq[np][2]);
            }
        }

        // epilogue: bias (SMEM) + STG
        const size_t row = (size_t)t * TILE_M + rbase_in_tile;
#pragma unroll
        for (int nt = 0; nt < 16; nt++) {
            const int col = nt * 8 + cpair;
            const float bxv = bsm[col], byv = bsm[col + 1];
            float2 v0 = make_float2(acc[nt][0] + bxv, acc[nt][1] + byv);
            float2 v1 = make_float2(acc[nt][2] + bxv, acc[nt][3] + byv);
            *(float2*)(y + row * D + col)       = v0;
            *(float2*)(y + (row + 8) * D + col) = v1;
        }
    }
}

// ============================================================================

extern "C" void kernel_launch(void* const* d_in, const int* in_sizes, int n_in,
                              void* d_out, int out_size) {
    const float* x    = (const float*)d_in[0];  // [16, 8192, 128]
    const float* W    = (const float*)d_in[1];  // [4, 128, 128]
    const float* b    = (const float*)d_in[2];  // [4, 128]
    const float* wsel = (const float*)d_in[3];  // [4]
    float* y = (float*)d_out;                   // [16, 8192, 128]

    static bool attr_set = false;
    if (!attr_set) {
        cudaFuncSetAttribute(gemm_kernel,
                             cudaFuncAttributeMaxDynamicSharedMemorySize, SM_TOTAL);
        attr_set = true;
    }
    gemm_kernel<<<GRID, NTHR, SM_TOTAL>>>(x, W, b, wsel, y);
}

// round 15
// speedup vs baseline: 1.1858x; 1.0703x over previous
#include <cuda_runtime.h>
#include <cuda_fp16.h>
#include <cstdint>

// ============================================================================
// y = x @ W_eff^T + b_eff   (exact collapse of the one-hot op mixture)
// x: [131072, 128] fp32.  Single fp16 product (rel_err ~2.9e-4).
// R15 = R14 with the n-permutation FIXED (R14 used 32-col blocks mapped into
//   16-position ranges -> collisions + SMEM OOB).  Correct mapping, per
//   16-column block:  f = 16k + 4m + u  ->  npos = 16k + (u<2 ? 2m+u
//   : 8+2m+(u-2)).  Lane-group m's 4 accumulator cols of n-tile pair k then
//   cover gmem cols 16k+4m..+3 -> epilogue is 16 STG.128 at stride 16.
//   Store wavefronts halve (256->128/warp/tile); per-tile L1 wf 5120->4096.
//   k-perm (R11) retained.  MMA loop identical to R11.
// ============================================================================

static constexpr int D       = 128;
static constexpr int TILE_M  = 128;
static constexpr int N_TILES = 1024;
static constexpr int GRID    = 148;                  // persistent, 1 CTA/SM
static constexpr int NTHR    = 256;                  // 8 warps x 16 rows

static constexpr int PITCHW  = 272;                  // fp16 W tile pitch
static constexpr int WTILE   = 128 * PITCHW;         // 34816 B
static constexpr int SM_W    = 0;
static constexpr int SM_BIAS = WTILE;                // 512 B
static constexpr int SM_TOTAL = WTILE + 512;

// ---------------- PTX helpers (baseline ISA only) ---------------------------

__device__ __forceinline__ uint32_t smem_to_u32(const void* p) {
    uint32_t a;
    asm("{ .reg .u64 t; cvta.to.shared.u64 t, %1; cvt.u32.u64 %0, t; }"
        : "=r"(a) : "l"(p));
    return a;
}

__device__ __forceinline__ void ldmatrix_x4(uint32_t& r0, uint32_t& r1,
                                            uint32_t& r2, uint32_t& r3,
                                            uint32_t addr) {
    asm volatile("ldmatrix.sync.aligned.m8n8.x4.shared.b16 {%0,%1,%2,%3}, [%4];"
                 : "=r"(r0), "=r"(r1), "=r"(r2), "=r"(r3) : "r"(addr));
}

__device__ __forceinline__ void mma_f16(float* c, const uint32_t* a,
                                        const uint32_t* b) {
    asm volatile(
        "mma.sync.aligned.m16n8k16.row.col.f32.f16.f16.f32 "
        "{%0,%1,%2,%3}, {%4,%5,%6,%7}, {%8,%9}, {%0,%1,%2,%3};"
        : "+f"(c[0]), "+f"(c[1]), "+f"(c[2]), "+f"(c[3])
        : "r"(a[0]), "r"(a[1]), "r"(a[2]), "r"(a[3]), "r"(b[0]), "r"(b[1]));
}

__device__ __forceinline__ uint32_t pack_h2(float a, float b) {
    __half2 h = __floats2half2_rn(a, b);
    return *(uint32_t*)&h;
}

// ============================================================================
__global__ void __launch_bounds__(NTHR, 1)
gemm_kernel(const float* __restrict__ x,
            const float* __restrict__ W,
            const float* __restrict__ bias,
            const float* __restrict__ wsel,
            float* __restrict__ y) {
    extern __shared__ char smem[];
    const uint32_t sb  = smem_to_u32(smem);
    const int tid  = threadIdx.x;
    const int w    = tid >> 5;       // warp 0..7 -> rows w*16 .. w*16+15
    const int l    = tid & 31;

    const float w0 = wsel[0], w1 = wsel[1], w2 = wsel[2], w3 = wsel[3];

    // ---- stage W_eff (fp16) into SMEM with BOTH permutations ----
    // col (k-perm): fragment-k (2j+m)<-data-k(4j+m); (2j+8+m)<-(4j+2+m).
    // row (n-perm): f = 16k+4m+u -> npos = 16k + (u<2 ? 2m+u : 8+2m+(u-2)).
#pragma unroll
    for (int jj = 0; jj < 64; jj++) {                // 16384 / 256
        const int idx = tid + jj * NTHR;
        const float v = w0 * W[idx] + w1 * W[16384 + idx]
                      + w2 * W[32768 + idx] + w3 * W[49152 + idx];
        const int f  = idx >> 7, d = idx & 127;
        // column permutation (k within 16-block)
        const int bblk = d >> 4, dk = d & 15;
        const int j  = dk >> 2, m = dk & 3;
        const int fk = 2 * j + m + ((m >= 2) ? 6 : 0);
        const int col = bblk * 16 + fk;
        // row permutation (output-column relabeling), 16-col blocks
        const int k = f >> 4, r = f & 15;
        const int q = r >> 2, u = r & 3;
        const int npos = 16 * k + ((u < 2) ? (2 * q + u) : (8 + 2 * q + (u - 2)));
        *(__half*)(smem + SM_W + npos * PITCHW + col * 2) = __float2half_rn(v);
    }
    if (tid < 128) {
        ((float*)(smem + SM_BIAS))[tid] =
            w0 * bias[tid] + w1 * bias[128 + tid]
          + w2 * bias[256 + tid] + w3 * bias[384 + tid];
    }
    __syncthreads();                 // the ONLY block-wide barrier

    // ---- per-lane bias float4s: cols 16k + 4*(l&3) .. +3, k = 0..7 ----
    const int m4 = (l & 3) * 4;
    float4 bb[8];
#pragma unroll
    for (int k = 0; k < 8; k++)
        bb[k] = *(const float4*)((const float*)(smem + SM_BIAS) + 16 * k + m4);

    // B ldmatrix per-lane offset (both permutations handled in staging)
    const uint32_t boff = (uint32_t)((((l >> 4) & 1) * 8 + (l & 7)) * PITCHW
                                     + ((l >> 3) & 1) * 16);
    const uint32_t sW = sb + SM_W;

    // per-thread A row/col: row = t*128 + w*16 + l/4, col floats (l&3)*4
    const int rbase_in_tile = w * 16 + (l >> 2);
    const int acol = (l & 3) * 4;

    for (int t = blockIdx.x; t < N_TILES; t += GRID) {
        const float* xr = x + ((size_t)t * TILE_M + rbase_in_tile) * D + acol;

        float acc[16][4];
#pragma unroll
        for (int nt = 0; nt < 16; nt++)
#pragma unroll
            for (int j = 0; j < 4; j++) acc[nt][j] = 0.0f;

#pragma unroll
        for (int ks = 0; ks < 8; ks++) {
            // A fragment: 2x LDG.128 (k-permuted mapping)
            const float4 lo = *(const float4*)(xr + ks * 16);          // row r
            const float4 hi = *(const float4*)(xr + 8 * D + ks * 16);  // row r+8
            uint32_t a[4];
            a[0] = pack_h2(lo.x, lo.y);
            a[1] = pack_h2(hi.x, hi.y);
            a[2] = pack_h2(lo.z, lo.w);
            a[3] = pack_h2(hi.z, hi.w);

            // B fragments: 8 x4-ldmatrix cover all 16 n-tiles
            uint32_t bq[8][4];
#pragma unroll
            for (int np = 0; np < 8; np++) {
                const uint32_t nb = (uint32_t)(np * 16) * PITCHW;
                ldmatrix_x4(bq[np][0], bq[np][1], bq[np][2], bq[np][3],
                            sW + boff + nb + (uint32_t)ks * 32);
            }

            // 16 MMAs into 16 independent accumulators
#pragma unroll
            for (int np = 0; np < 8; np++) {
                mma_f16(acc[np * 2 + 0], a, &bq[np][0]);
                mma_f16(acc[np * 2 + 1], a, &bq[np][2]);
            }
        }

        // epilogue: n-tile pair (2k,2k+1) regs {0,1} cover gmem cols
        // 16k+4m..+3 (rows r, r+8 via regs {2,3}): two STG.128 per pair.
        const size_t row = (size_t)t * TILE_M + rbase_in_tile;
        float* y0 = y + row * D + m4;
        float* y1 = y + (row + 8) * D + m4;
#pragma unroll
        for (int k = 0; k < 8; k++) {
            float4 v0, v1;
            v0.x = acc[2 * k][0]     + bb[k].x;
            v0.y = acc[2 * k][1]     + bb[k].y;
            v0.z = acc[2 * k + 1][0] + bb[k].z;
            v0.w = acc[2 * k + 1][1] + bb[k].w;
            v1.x = acc[2 * k][2]     + bb[k].x;
            v1.y = acc[2 * k][3]     + bb[k].y;
            v1.z = acc[2 * k + 1][2] + bb[k].z;
            v1.w = acc[2 * k + 1][3] + bb[k].w;
            *(float4*)(y0 + 16 * k) = v0;
            *(float4*)(y1 + 16 * k) = v1;
        }
    }
}

// ============================================================================

extern "C" void kernel_launch(void* const* d_in, const int* in_sizes, int n_in,
                              void* d_out, int out_size) {
    const float* x    = (const float*)d_in[0];  // [16, 8192, 128]
    const float* W    = (const float*)d_in[1];  // [4, 128, 128]
    const float* b    = (const float*)d_in[2];  // [4, 128]
    const float* wsel = (const float*)d_in[3];  // [4]
    float* y = (float*)d_out;                   // [16, 8192, 128]

    static bool attr_set = false;
    if (!attr_set) {
        cudaFuncSetAttribute(gemm_kernel,
                             cudaFuncAttributeMaxDynamicSharedMemorySize, SM_TOTAL);
        attr_set = true;
    }
    gemm_kernel<<<GRID, NTHR, SM_TOTAL>>>(x, W, b, wsel, y);
}

// round 16
// speedup vs baseline: 1.1950x; 1.0078x over previous
#include <cuda_runtime.h>
#include <cuda_fp16.h>
#include <cstdint>

// ============================================================================
// y = x @ W_eff^T + b_eff   (exact collapse of the one-hot op mixture)
// x: [131072, 128] fp32.  Single fp16 product (rel_err ~2.9e-4).
// R16 = R15 + SOFTWARE-PIPELINED A LOADS (register double-buffer, depth 1):
//   each k-step issues ks+1's two LDG.128 first (next tile's ks=0 on the
//   last step), then packs/MMAs the previous loads -> the load has a full
//   k-step of B-ldmatrix+MMA work to complete; exposed L2/DRAM latency per
//   k-step ~0.  R15's both-permutation W staging + STG.128 epilogue kept.
// ============================================================================

static constexpr int D       = 128;
static constexpr int TILE_M  = 128;
static constexpr int N_TILES = 1024;
static constexpr int GRID    = 148;                  // persistent, 1 CTA/SM
static constexpr int NTHR    = 256;                  // 8 warps x 16 rows

static constexpr int PITCHW  = 272;                  // fp16 W tile pitch
static constexpr int WTILE   = 128 * PITCHW;         // 34816 B
static constexpr int SM_W    = 0;
static constexpr int SM_BIAS = WTILE;                // 512 B
static constexpr int SM_TOTAL = WTILE + 512;

// ---------------- PTX helpers (baseline ISA only) ---------------------------

__device__ __forceinline__ uint32_t smem_to_u32(const void* p) {
    uint32_t a;
    asm("{ .reg .u64 t; cvta.to.shared.u64 t, %1; cvt.u32.u64 %0, t; }"
        : "=r"(a) : "l"(p));
    return a;
}

__device__ __forceinline__ void ldmatrix_x4(uint32_t& r0, uint32_t& r1,
                                            uint32_t& r2, uint32_t& r3,
                                            uint32_t addr) {
    asm volatile("ldmatrix.sync.aligned.m8n8.x4.shared.b16 {%0,%1,%2,%3}, [%4];"
                 : "=r"(r0), "=r"(r1), "=r"(r2), "=r"(r3) : "r"(addr));
}

__device__ __forceinline__ void mma_f16(float* c, const uint32_t* a,
                                        const uint32_t* b) {
    asm volatile(
        "mma.sync.aligned.m16n8k16.row.col.f32.f16.f16.f32 "
        "{%0,%1,%2,%3}, {%4,%5,%6,%7}, {%8,%9}, {%0,%1,%2,%3};"
        : "+f"(c[0]), "+f"(c[1]), "+f"(c[2]), "+f"(c[3])
        : "r"(a[0]), "r"(a[1]), "r"(a[2]), "r"(a[3]), "r"(b[0]), "r"(b[1]));
}

__device__ __forceinline__ uint32_t pack_h2(float a, float b) {
    __half2 h = __floats2half2_rn(a, b);
    return *(uint32_t*)&h;
}

// ============================================================================
__global__ void __launch_bounds__(NTHR, 1)
gemm_kernel(const float* __restrict__ x,
            const float* __restrict__ W,
            const float* __restrict__ bias,
            const float* __restrict__ wsel,
            float* __restrict__ y) {
    extern __shared__ char smem[];
    const uint32_t sb  = smem_to_u32(smem);
    const int tid  = threadIdx.x;
    const int w    = tid >> 5;       // warp 0..7 -> rows w*16 .. w*16+15
    const int l    = tid & 31;

    const float w0 = wsel[0], w1 = wsel[1], w2 = wsel[2], w3 = wsel[3];

    // ---- stage W_eff (fp16) into SMEM with BOTH permutations ----
    // col (k-perm): fragment-k (2j+m)<-data-k(4j+m); (2j+8+m)<-(4j+2+m).
    // row (n-perm): f = 16k+4m+u -> npos = 16k + (u<2 ? 2m+u : 8+2m+(u-2)).
#pragma unroll
    for (int jj = 0; jj < 64; jj++) {                // 16384 / 256
        const int idx = tid + jj * NTHR;
        const float v = w0 * W[idx] + w1 * W[16384 + idx]
                      + w2 * W[32768 + idx] + w3 * W[49152 + idx];
        const int f  = idx >> 7, d = idx & 127;
        const int bblk = d >> 4, dk = d & 15;
        const int j  = dk >> 2, m = dk & 3;
        const int fk = 2 * j + m + ((m >= 2) ? 6 : 0);
        const int col = bblk * 16 + fk;
        const int k = f >> 4, r = f & 15;
        const int q = r >> 2, u = r & 3;
        const int npos = 16 * k + ((u < 2) ? (2 * q + u) : (8 + 2 * q + (u - 2)));
        *(__half*)(smem + SM_W + npos * PITCHW + col * 2) = __float2half_rn(v);
    }
    if (tid < 128) {
        ((float*)(smem + SM_BIAS))[tid] =
            w0 * bias[tid] + w1 * bias[128 + tid]
          + w2 * bias[256 + tid] + w3 * bias[384 + tid];
    }
    __syncthreads();                 // the ONLY block-wide barrier

    // ---- per-lane bias float4s: cols 16k + 4*(l&3) .. +3, k = 0..7 ----
    const int m4 = (l & 3) * 4;
    float4 bb[8];
#pragma unroll
    for (int k = 0; k < 8; k++)
        bb[k] = *(const float4*)((const float*)(smem + SM_BIAS) + 16 * k + m4);

    // B ldmatrix per-lane offset (both permutations handled in staging)
    const uint32_t boff = (uint32_t)((((l >> 4) & 1) * 8 + (l & 7)) * PITCHW
                                     + ((l >> 3) & 1) * 16);
    const uint32_t sW = sb + SM_W;

    // per-thread A row/col: row = t*128 + w*16 + l/4, col floats (l&3)*4
    const int rbase_in_tile = w * 16 + (l >> 2);
    const int acol = (l & 3) * 4;

    // ---- A pipeline prologue: load tile t0 / ks0 ----
    int t0 = blockIdx.x;
    const float* xr = x + ((size_t)t0 * TILE_M + rbase_in_tile) * D + acol;
    float4 lo = *(const float4*)(xr);
    float4 hi = *(const float4*)(xr + 8 * D);

    for (int t = t0; t < N_TILES; t += GRID) {
        // next tile's base row pointer (clamped: reload current on last tile)
        const int tn = (t + GRID < N_TILES) ? (t + GRID) : t;
        const float* xrn = x + ((size_t)tn * TILE_M + rbase_in_tile) * D + acol;

        float acc[16][4];
#pragma unroll
        for (int nt = 0; nt < 16; nt++)
#pragma unroll
            for (int j = 0; j < 4; j++) acc[nt][j] = 0.0f;

#pragma unroll
        for (int ks = 0; ks < 8; ks++) {
            // 1) prefetch next k-step's A (or next tile's ks=0)
            const float* pn = (ks < 7) ? (xr + (ks + 1) * 16) : xrn;
            const float4 nlo = *(const float4*)(pn);
            const float4 nhi = *(const float4*)(pn + 8 * D);

            // 2) pack previous loads into the fragment
            uint32_t a[4];
            a[0] = pack_h2(lo.x, lo.y);
            a[1] = pack_h2(hi.x, hi.y);
            a[2] = pack_h2(lo.z, lo.w);
            a[3] = pack_h2(hi.z, hi.w);

            // 3) B fragments: 8 x4-ldmatrix cover all 16 n-tiles
            uint32_t bq[8][4];
#pragma unroll
            for (int np = 0; np < 8; np++) {
                const uint32_t nb = (uint32_t)(np * 16) * PITCHW;
                ldmatrix_x4(bq[np][0], bq[np][1], bq[np][2], bq[np][3],
                            sW + boff + nb + (uint32_t)ks * 32);
            }

            // 4) 16 MMAs into 16 independent accumulators
#pragma unroll
            for (int np = 0; np < 8; np++) {
                mma_f16(acc[np * 2 + 0], a, &bq[np][0]);
                mma_f16(acc[np * 2 + 1], a, &bq[np][2]);
            }

            // 5) rotate the A double-buffer
            lo = nlo;
            hi = nhi;
        }

        // epilogue: n-tile pair (2k,2k+1) covers gmem cols 16k+4m..+3
        const size_t row = (size_t)t * TILE_M + rbase_in_tile;
        float* y0 = y + row * D + m4;
        float* y1 = y + (row + 8) * D + m4;
#pragma unroll
        for (int k = 0; k < 8; k++) {
            float4 v0, v1;
            v0.x = acc[2 * k][0]     + bb[k].x;
            v0.y = acc[2 * k][1]     + bb[k].y;
            v0.z = acc[2 * k + 1][0] + bb[k].z;
            v0.w = acc[2 * k + 1][1] + bb[k].w;
            v1.x = acc[2 * k][2]     + bb[k].x;
            v1.y = acc[2 * k][3]     + bb[k].y;
            v1.z = acc[2 * k + 1][2] + bb[k].z;
            v1.w = acc[2 * k + 1][3] + bb[k].w;
            *(float4*)(y0 + 16 * k) = v0;
            *(float4*)(y1 + 16 * k) = v1;
        }

        xr = xrn;                    // advance the A stream
    }
}

// ============================================================================

extern "C" void kernel_launch(void* const* d_in, const int* in_sizes, int n_in,
                              void* d_out, int out_size) {
    const float* x    = (const float*)d_in[0];  // [16, 8192, 128]
    const float* W    = (const float*)d_in[1];  // [4, 128, 128]
    const float* b    = (const float*)d_in[2];  // [4, 128]
    const float* wsel = (const float*)d_in[3];  // [4]
    float* y = (float*)d_out;                   // [16, 8192, 128]

    static bool attr_set = false;
    if (!attr_set) {
        cudaFuncSetAttribute(gemm_kernel,
                             cudaFuncAttributeMaxDynamicSharedMemorySize, SM_TOTAL);
        attr_set = true;
    }
    gemm_kernel<<<GRID, NTHR, SM_TOTAL>>>(x, W, b, wsel, y);
}